// round 13
// baseline (speedup 1.0000x reference)
#include <cuda_runtime.h>
#include <cstdint>

// SynergyPre on GB300 — R13: occupancy push #2. TPB=160, TILE=320, 3 CTAs/SM
// (15 warps vs 12). Same EPT=2 conflict-free XOR-swizzled staging + f32x2
// orientation as R12.
// out = [x(E), label(E)] fp32. Edges int32. cell/proj inputs dead code.

#define TPB   160
#define TILE  320
#define SROW  320            // sL row stride in words
#define NCH   4              // 4 chunks x 32 features

typedef unsigned long long u64;

#define SM_L     0                      // 32 * 320 * 4 = 40960
#define SM_IDX   40960                  // 320 * 16     = 5120
#define SM_W1T   (SM_IDX + 5120)        // 16384  [d][j]
#define SM_W2T   (SM_W1T + 16384)       // 4096   [k][j]
#define SM_W3T   (SM_W2T + 4096)        // 4096
#define SM_TOTAL (SM_W3T + 4096)        // 70656 bytes

__device__ __forceinline__ u64 fma2(u64 a, u64 b, u64 c) {
    u64 d; asm("fma.rn.f32x2 %0, %1, %2, %3;" : "=l"(d) : "l"(a), "l"(b), "l"(c)); return d;
}
__device__ __forceinline__ u64 splat2(float x) {
    u64 d; asm("mov.b64 %0, {%1, %1};" : "=l"(d) : "f"(x)); return d;
}
__device__ __forceinline__ float2 unpk2(u64 v) {
    float2 r; asm("mov.b64 {%0, %1}, %2;" : "=f"(r.x), "=f"(r.y) : "l"(v)); return r;
}
// conflict-free staging address (words)
__device__ __forceinline__ int swz(int row, int col) { return row * SROW + (col ^ (row & 28)); }

// 32->32 layer, 2 edges/thread: h rows from sL (thread's 2 swizzled cols),
// weight j-pairs direct from ulonglong2 LDS.128, relu, spill back.
#define MLP_LAYER(WT, BIAS)                                                           \
  { const u64* bp = (const u64*)(BIAS);                                               \
    _Pragma("unroll")                                                                 \
    for (int jp = 0; jp < 16; jp++) {                                                 \
        const u64 b = __ldg(bp + jp);                                                 \
        ac0[jp] = b; ac1[jp] = b; }                                                   \
    _Pragma("unroll 4")                                                               \
    for (int k = 0; k < 32; k++) {                                                    \
        const float2 lp = *(const float2*)(sL + swz(k, 2 * tid));                     \
        const u64 s0 = splat2(lp.x), s1 = splat2(lp.y);                               \
        const ulonglong2* wr = (const ulonglong2*)((WT) + k * 32);                    \
        _Pragma("unroll")                                                             \
        for (int q = 0; q < 8; q++) {                                                 \
            const ulonglong2 w = wr[q];                                               \
            ac0[2*q]=fma2(w.x,s0,ac0[2*q]); ac0[2*q+1]=fma2(w.y,s0,ac0[2*q+1]);       \
            ac1[2*q]=fma2(w.x,s1,ac1[2*q]); ac1[2*q+1]=fma2(w.y,s1,ac1[2*q+1]); } }   \
    _Pragma("unroll")                                                                 \
    for (int jp = 0; jp < 16; jp++) {                                                 \
        const float2 f0 = unpk2(ac0[jp]), f1 = unpk2(ac1[jp]);                        \
        float2 vA, vB;                                                                \
        vA.x = fmaxf(f0.x, 0.f); vA.y = fmaxf(f1.x, 0.f);                             \
        vB.x = fmaxf(f0.y, 0.f); vB.y = fmaxf(f1.y, 0.f);                             \
        *(float2*)(sL + swz(2*jp,     2 * tid)) = vA;                                 \
        *(float2*)(sL + swz(2*jp + 1, 2 * tid)) = vB; } }

__global__ __launch_bounds__(TPB, 3)
void synergy_kernel(const float* __restrict__ drug,   // [4096,128]
                    const int* __restrict__ edges,    // [E,4] int32
                    const float* __restrict__ W1, const float* __restrict__ b1,
                    const float* __restrict__ W2, const float* __restrict__ b2,
                    const float* __restrict__ W3, const float* __restrict__ b3,
                    const float* __restrict__ W4, const float* __restrict__ b4,
                    float* __restrict__ out, int E)
{
    extern __shared__ char smc[];
    float* sL   = (float*)(smc + SM_L);
    int4*  sIdx = (int4*)(smc + SM_IDX);
    float* sW1t = (float*)(smc + SM_W1T);
    float* sW2t = (float*)(smc + SM_W2T);
    float* sW3t = (float*)(smc + SM_W3T);

    const int tid = threadIdx.x, lane = tid & 31, wid = tid >> 5;

    // ---- stage transposed weights + edge indices ----
    for (int i = tid; i < 32 * 128; i += TPB) {
        const int j = i >> 7, d = i & 127;
        sW1t[d * 32 + j] = W1[i];
    }
    for (int i = tid; i < 32 * 32; i += TPB) {
        const int j = i >> 5, k = i & 31;
        sW2t[k * 32 + j] = W2[i];
        sW3t[k * 32 + j] = W3[i];
    }
    const int base = blockIdx.x * TILE;
    for (int i = tid; i < TILE; i += TPB) {
        const int e = base + i;
        sIdx[i] = ((const int4*)edges)[e < E ? e : E - 1];
    }
    __syncthreads();

    // ---- layer-1 accumulators: 2 edges x 16 j-pairs, init with bias ----
    u64 ac0[16], ac1[16];
    {
        const u64* bp = (const u64*)b1;
        #pragma unroll
        for (int jp = 0; jp < 16; jp++) {
            const u64 b = __ldg(bp + jp);
            ac0[jp] = b; ac1[jp] = b;
        }
    }

    const int e4 = lane >> 3, f8 = lane & 7;
    const int ebw = wid * 64;                 // 64 edges per warp (5 warps x 64 = 320)

    for (int ch = 0; ch < NCH; ch++) {
        // ---- Phase A: coalesced gather -> product -> swizzled sL[feat][edge] ----
        const int fo = ch * 32 + f8 * 4;
        const int r0 = f8 * 4;
        #pragma unroll 2
        for (int i = 0; i < 16; i++) {
            const int el  = ebw + i * 4 + e4;
            const int4 id = sIdx[el];
            const float4 va = __ldg((const float4*)(drug + (size_t)id.x * 128 + fo));
            const float4 vb = __ldg((const float4*)(drug + (size_t)id.y * 128 + fo));
            const float4 vc = __ldg((const float4*)(drug + (size_t)id.z * 128 + fo));
            sL[swz(r0 + 0, el)] = va.x * vb.x * vc.x;
            sL[swz(r0 + 1, el)] = va.y * vb.y * vc.y;
            sL[swz(r0 + 2, el)] = va.z * vb.z * vc.z;
            sL[swz(r0 + 3, el)] = va.w * vb.w * vc.w;
        }
        __syncthreads();

        // ---- Phase B: layer-1 partial over 32 features ----
        const float* wb = sW1t + ch * 32 * 32;
        #pragma unroll 4
        for (int d = 0; d < 32; d++) {
            const float2 lp = *(const float2*)(sL + swz(d, 2 * tid));
            const u64 s0 = splat2(lp.x), s1 = splat2(lp.y);
            const ulonglong2* wr = (const ulonglong2*)(wb + d * 32);
            #pragma unroll
            for (int q = 0; q < 8; q++) {
                const ulonglong2 w = wr[q];
                ac0[2*q]=fma2(w.x,s0,ac0[2*q]); ac0[2*q+1]=fma2(w.y,s0,ac0[2*q+1]);
                ac1[2*q]=fma2(w.x,s1,ac1[2*q]); ac1[2*q+1]=fma2(w.y,s1,ac1[2*q+1]);
            }
        }
        if (ch < NCH - 1) __syncthreads();
    }

    // ---- layer-1 relu -> spill h (thread-private swizzled cols; no sync) ----
    #pragma unroll
    for (int jp = 0; jp < 16; jp++) {
        const float2 f0 = unpk2(ac0[jp]), f1 = unpk2(ac1[jp]);
        float2 vA, vB;
        vA.x = fmaxf(f0.x, 0.f); vA.y = fmaxf(f1.x, 0.f);
        vB.x = fmaxf(f0.y, 0.f); vB.y = fmaxf(f1.y, 0.f);
        *(float2*)(sL + swz(2*jp,     2 * tid)) = vA;
        *(float2*)(sL + swz(2*jp + 1, 2 * tid)) = vB;
    }

    // ---- layers 2 and 3 ----
    MLP_LAYER(sW2t, b2)
    MLP_LAYER(sW3t, b3)

    // ---- layer 4 + sigmoid ----
    const float bb4 = __ldg(b4);
    float z0 = bb4, z1 = bb4;
    #pragma unroll 8
    for (int k = 0; k < 32; k++) {
        const float2 lp = *(const float2*)(sL + swz(k, 2 * tid));
        const float w = __ldg(W4 + k);
        z0 = fmaf(w, lp.x, z0); z1 = fmaf(w, lp.y, z1);
    }
    float2 xv;
    xv.x = __fdividef(1.0f, 1.0f + __expf(-z0));
    xv.y = __fdividef(1.0f, 1.0f + __expf(-z1));

    float2 lb;
    lb.x = (float)sIdx[2*tid + 0].w;
    lb.y = (float)sIdx[2*tid + 1].w;

    const int e0 = base + 2 * tid;
    if (e0 + 1 < E) {
        *(float2*)(out + e0)     = xv;
        *(float2*)(out + E + e0) = lb;
    } else if (e0 < E) {
        out[e0]     = xv.x;
        out[E + e0] = lb.x;
    }
}

extern "C" void kernel_launch(void* const* d_in, const int* in_sizes, int n_in,
                              void* d_out, int out_size)
{
    const float* drug  = (const float*)d_in[0];
    const int*   edges = (const int*)d_in[2];
    const float* W1 = (const float*)d_in[5];
    const float* b1 = (const float*)d_in[6];
    const float* W2 = (const float*)d_in[7];
    const float* b2 = (const float*)d_in[8];
    const float* W3 = (const float*)d_in[9];
    const float* b3 = (const float*)d_in[10];
    const float* W4 = (const float*)d_in[11];
    const float* b4 = (const float*)d_in[12];

    const int E = in_sizes[2] / 4;
    float* out = (float*)d_out;

    static int attr_set = 0;
    if (!attr_set) {
        cudaFuncSetAttribute(synergy_kernel,
                             cudaFuncAttributeMaxDynamicSharedMemorySize, SM_TOTAL);
        attr_set = 1;
    }
    const int grid = (E + TILE - 1) / TILE;
    synergy_kernel<<<grid, TPB, SM_TOTAL>>>(drug, edges, W1, b1, W2, b2, W3, b3,
                                            W4, b4, out, E);
}

// round 17
// speedup vs baseline: 1.1802x; 1.1802x over previous
#include <cuda_runtime.h>
#include <cstdint>

// SynergyPre on GB300 — R16: R15 with the column map fixed to the injective
// XOR form CM(c) = c ^ ((c>>3)&4) (R15's additive skew collided groups at
// bit-5 boundaries: CM(60..63)==CM(64..67)). fhi half is at colbase^4.
// Register-tiled 8j x 8e GEMM for layers 1-3: per k, 4 LDS.128 feed 32 fma2.
// TPB=128, TILE=256, 3 CTAs/SM. out = [x(E), label(E)] fp32. Edges int32.

#define TPB   128
#define TILE  256
#define SROW  256            // XOR map keeps columns in 0..255; 256 % 32 == 0
#define NCH   4

typedef unsigned long long u64;

#define SM_L     0                      // 32 * 256 * 4 = 32768
#define SM_IDX   32768                  // 256 * 16     = 4096
#define SM_W1T   36864                  // 16384  [k][j]
#define SM_W2T   53248                  // 4096   [k][j]
#define SM_W3T   57344                  // 4096
#define SM_TOTAL 61440

__device__ __forceinline__ u64 fma2(u64 a, u64 b, u64 c) {
    u64 d; asm("fma.rn.f32x2 %0, %1, %2, %3;" : "=l"(d) : "l"(a), "l"(b), "l"(c)); return d;
}
__device__ __forceinline__ u64 splat2(float x) {
    u64 d; asm("mov.b64 %0, {%1, %1};" : "=l"(d) : "f"(x)); return d;
}
__device__ __forceinline__ float2 unpk2(u64 v) {
    float2 r; asm("mov.b64 {%0, %1}, %2;" : "=f"(r.x), "=f"(r.y) : "l"(v)); return r;
}
// injective column map: XOR bit5 into bit2 (half-swap within each 8-group)
__device__ __forceinline__ int CM(int c)            { return c ^ ((c >> 3) & 4); }
__device__ __forceinline__ int sw(int row, int cm)  { return row * SROW + (cm ^ (row & 28)); }

// per-k body: 2 weight LDS.128 (uniform per quarter-warp) + 2 logit LDS.128
// (conflict-free) -> 32 fma2 (8j x 8e / 2)
#define L_BODY(WB)                                                             \
  { const ulonglong2* wr = (const ulonglong2*)((WB) + k * 32 + tj * 8);        \
    const ulonglong2 wA = wr[0], wB2 = wr[1];                                  \
    const float4 flo = *(const float4*)(sL + sw(k, colbase));                  \
    const float4 fhi = *(const float4*)(sL + sw(k, colbase ^ 4));              \
    const float lv[8] = {flo.x, flo.y, flo.z, flo.w, fhi.x, fhi.y, fhi.z, fhi.w}; \
    _Pragma("unroll")                                                          \
    for (int e = 0; e < 8; e++) {                                              \
      const u64 s = splat2(lv[e]);                                             \
      acc[0][e] = fma2(wA.x,  s, acc[0][e]);                                   \
      acc[1][e] = fma2(wA.y,  s, acc[1][e]);                                   \
      acc[2][e] = fma2(wB2.x, s, acc[2][e]);                                   \
      acc[3][e] = fma2(wB2.y, s, acc[3][e]); } }

#define ACC_INIT(B)                                                            \
  { const u64* bp = (const u64*)(B);                                           \
    _Pragma("unroll")                                                          \
    for (int jp = 0; jp < 4; jp++) {                                           \
      const u64 bv = __ldg(bp + tj * 4 + jp);                                  \
      _Pragma("unroll")                                                        \
      for (int e = 0; e < 8; e++) acc[jp][e] = bv; } }

// relu + store thread tile (8j x 8e) back to sL rows tj*8..+8
#define EPI_STORE()                                                            \
  { _Pragma("unroll")                                                          \
    for (int jp = 0; jp < 4; jp++) {                                           \
      const int j0 = tj * 8 + 2 * jp;                                          \
      const float2 t0 = unpk2(acc[jp][0]), t1 = unpk2(acc[jp][1]);             \
      const float2 t2 = unpk2(acc[jp][2]), t3 = unpk2(acc[jp][3]);             \
      const float2 t4 = unpk2(acc[jp][4]), t5 = unpk2(acc[jp][5]);             \
      const float2 t6 = unpk2(acc[jp][6]), t7 = unpk2(acc[jp][7]);             \
      float4 v;                                                                \
      v.x=fmaxf(t0.x,0.f); v.y=fmaxf(t1.x,0.f); v.z=fmaxf(t2.x,0.f); v.w=fmaxf(t3.x,0.f); \
      *(float4*)(sL + sw(j0, colbase)) = v;                                    \
      v.x=fmaxf(t4.x,0.f); v.y=fmaxf(t5.x,0.f); v.z=fmaxf(t6.x,0.f); v.w=fmaxf(t7.x,0.f); \
      *(float4*)(sL + sw(j0, colbase ^ 4)) = v;                                \
      v.x=fmaxf(t0.y,0.f); v.y=fmaxf(t1.y,0.f); v.z=fmaxf(t2.y,0.f); v.w=fmaxf(t3.y,0.f); \
      *(float4*)(sL + sw(j0 + 1, colbase)) = v;                                \
      v.x=fmaxf(t4.y,0.f); v.y=fmaxf(t5.y,0.f); v.z=fmaxf(t6.y,0.f); v.w=fmaxf(t7.y,0.f); \
      *(float4*)(sL + sw(j0 + 1, colbase ^ 4)) = v; } }

#define LAYER32(WT, B)                                                         \
  ACC_INIT(B);                                                                 \
  { _Pragma("unroll 4")                                                        \
    for (int k = 0; k < 32; k++) L_BODY(WT) }                                  \
  __syncthreads();                                                             \
  EPI_STORE();                                                                 \
  __syncthreads();

__global__ __launch_bounds__(TPB, 3)
void synergy_kernel(const float* __restrict__ drug,   // [4096,128]
                    const int* __restrict__ edges,    // [E,4] int32
                    const float* __restrict__ W1, const float* __restrict__ b1,
                    const float* __restrict__ W2, const float* __restrict__ b2,
                    const float* __restrict__ W3, const float* __restrict__ b3,
                    const float* __restrict__ W4, const float* __restrict__ b4,
                    float* __restrict__ out, int E)
{
    extern __shared__ char smc[];
    float* sL   = (float*)(smc + SM_L);
    int4*  sIdx = (int4*)(smc + SM_IDX);
    float* sW1t = (float*)(smc + SM_W1T);
    float* sW2t = (float*)(smc + SM_W2T);
    float* sW3t = (float*)(smc + SM_W3T);

    const int tid = threadIdx.x, lane = tid & 31, wid = tid >> 5;
    const int tj = (tid >> 3) & 3;                       // j-slice: uniform per quarter-warp
    const int te = (tid & 7) | ((tid >> 5) << 3);        // e-group 0..31
    const int colbase = te * 8 + (te & 4);               // = CM(te*8)

    // ---- stage transposed weights [k][j] + edge indices ----
    for (int i = tid; i < 32 * 128; i += TPB) {
        const int j = i >> 7, d = i & 127;
        sW1t[d * 32 + j] = W1[i];
    }
    for (int i = tid; i < 32 * 32; i += TPB) {
        const int j = i >> 5, k = i & 31;
        sW2t[k * 32 + j] = W2[i];
        sW3t[k * 32 + j] = W3[i];
    }
    const int base = blockIdx.x * TILE;
    for (int i = tid; i < TILE; i += TPB) {
        const int e = base + i;
        sIdx[i] = ((const int4*)edges)[e < E ? e : E - 1];
    }
    __syncthreads();

    // ---- Layer 1: chunked K=128 ----
    u64 acc[4][8];
    ACC_INIT(b1);

    const int e4 = lane >> 3, f8 = lane & 7;
    const int ebw = wid * 64;

    for (int ch = 0; ch < NCH; ch++) {
        // Phase A: coalesced gather -> product -> staged sL[feat][edge]
        const int fo = ch * 32 + f8 * 4;
        const int r0 = f8 * 4;
        #pragma unroll 2
        for (int i = 0; i < 16; i++) {
            const int el  = ebw + i * 4 + e4;
            const int4 id = sIdx[el];
            const float4 va = __ldg((const float4*)(drug + (size_t)id.x * 128 + fo));
            const float4 vb = __ldg((const float4*)(drug + (size_t)id.y * 128 + fo));
            const float4 vc = __ldg((const float4*)(drug + (size_t)id.z * 128 + fo));
            const int cme = CM(el);
            sL[sw(r0 + 0, cme)] = va.x * vb.x * vc.x;
            sL[sw(r0 + 1, cme)] = va.y * vb.y * vc.y;
            sL[sw(r0 + 2, cme)] = va.z * vb.z * vc.z;
            sL[sw(r0 + 3, cme)] = va.w * vb.w * vc.w;
        }
        __syncthreads();

        // Phase B: tiled layer-1 partial over 32 features
        const float* wb = sW1t + ch * 32 * 32;
        #pragma unroll 4
        for (int k = 0; k < 32; k++) L_BODY(wb)
        __syncthreads();
    }
    EPI_STORE();
    __syncthreads();

    // ---- Layers 2 and 3 (tiled) ----
    LAYER32(sW2t, b2)
    LAYER32(sW3t, b3)

    // ---- Layer 4 + sigmoid (per-edge, 2 edges/thread) ----
    const int cm2t = CM(2 * tid);
    const float bb4 = __ldg(b4);
    float z0 = bb4, z1 = bb4;
    #pragma unroll 8
    for (int k = 0; k < 32; k++) {
        const float2 lp = *(const float2*)(sL + sw(k, cm2t));
        const float w = __ldg(W4 + k);
        z0 = fmaf(w, lp.x, z0); z1 = fmaf(w, lp.y, z1);
    }
    float2 xv;
    xv.x = __fdividef(1.0f, 1.0f + __expf(-z0));
    xv.y = __fdividef(1.0f, 1.0f + __expf(-z1));

    float2 lb;
    lb.x = (float)sIdx[2 * tid + 0].w;
    lb.y = (float)sIdx[2 * tid + 1].w;

    const int e0 = base + 2 * tid;
    if (e0 + 1 < E) {
        *(float2*)(out + e0)     = xv;
        *(float2*)(out + E + e0) = lb;
    } else if (e0 < E) {
        out[e0]     = xv.x;
        out[E + e0] = lb.x;
    }
}

extern "C" void kernel_launch(void* const* d_in, const int* in_sizes, int n_in,
                              void* d_out, int out_size)
{
    const float* drug  = (const float*)d_in[0];
    const int*   edges = (const int*)d_in[2];
    const float* W1 = (const float*)d_in[5];
    const float* b1 = (const float*)d_in[6];
    const float* W2 = (const float*)d_in[7];
    const float* b2 = (const float*)d_in[8];
    const float* W3 = (const float*)d_in[9];
    const float* b3 = (const float*)d_in[10];
    const float* W4 = (const float*)d_in[11];
    const float* b4 = (const float*)d_in[12];

    const int E = in_sizes[2] / 4;
    float* out = (float*)d_out;

    static int attr_set = 0;
    if (!attr_set) {
        cudaFuncSetAttribute(synergy_kernel,
                             cudaFuncAttributeMaxDynamicSharedMemorySize, SM_TOTAL);
        attr_set = 1;
    }
    const int grid = (E + TILE - 1) / TILE;
    synergy_kernel<<<grid, TPB, SM_TOTAL>>>(drug, edges, W1, b1, W2, b2, W3, b3,
                                            W4, b4, out, E);
}